// round 4
// baseline (speedup 1.0000x reference)
#include <cuda_runtime.h>
#include <cstdint>

// Problem shape (fixed by the dataset)
#define NMAX 100000
#define EMAX 1600000
#define INC 128
#define HIDC 128
#define OUTC 64

// ---------------- scratch (no allocation allowed) ----------------
__device__ float g_h1[(size_t)NMAX * HIDC];   // x@W1 (unscaled)
__device__ float g_hr[(size_t)NMAX * HIDC];   // relu(agg1 + b1)
__device__ float g_h2[(size_t)NMAX * OUTC];   // hr@W2 (unscaled)
__device__ float g_dinv[NMAX];
__device__ int   g_cnt_in[NMAX];
__device__ int   g_cnt_out[NMAX];
__device__ int   g_rowstart[NMAX];
__device__ int   g_cursor[NMAX];
__device__ int   g_bsum[1024];
__device__ int   g_csr[EMAX];

// ---------------- helpers ----------------
__device__ __forceinline__ uint32_t cvt_tf32(float f) {
    uint32_t r;
    asm("cvt.rna.tf32.f32 %0, %1;" : "=r"(r) : "f"(f));
    return r;
}

__device__ __forceinline__ void mma_tf32(float* c, const uint32_t* a, const uint32_t* b) {
    asm volatile(
        "mma.sync.aligned.m16n8k8.row.col.f32.tf32.tf32.f32 "
        "{%0,%1,%2,%3}, {%4,%5,%6,%7}, {%8,%9}, {%0,%1,%2,%3};"
        : "+f"(c[0]), "+f"(c[1]), "+f"(c[2]), "+f"(c[3])
        : "r"(a[0]), "r"(a[1]), "r"(a[2]), "r"(a[3]), "r"(b[0]), "r"(b[1]));
}

// ---------------- CSR build ----------------
__global__ void zero_kernel(int n) {
    int i = blockIdx.x * blockDim.x + threadIdx.x;
    if (i < n) { g_cnt_in[i] = 0; g_cnt_out[i] = 0; }
}

__global__ void hist_kernel(const int* __restrict__ ei, int E) {
    int e = blockIdx.x * blockDim.x + threadIdx.x;
    if (e < E) {
        atomicAdd(&g_cnt_out[ei[e]], 1);      // src -> out-degree (normalization)
        atomicAdd(&g_cnt_in[ei[E + e]], 1);   // dst -> in-degree (CSR)
    }
}

// warp-shuffle block scan (1024 threads): exclusive result + block total
__global__ void scan_block_kernel(int n) {
    __shared__ int wsum[32];
    int t = threadIdx.x, lane = t & 31, w = t >> 5;
    int gid = blockIdx.x * 1024 + t;
    int v = (gid < n) ? g_cnt_in[gid] : 0;
    int x = v;
    #pragma unroll
    for (int d = 1; d < 32; d <<= 1) {
        int y = __shfl_up_sync(0xFFFFFFFFu, x, d);
        if (lane >= d) x += y;
    }
    if (lane == 31) wsum[w] = x;
    __syncthreads();
    if (w == 0) {
        int s = wsum[lane];
        int xs = s;
        #pragma unroll
        for (int d = 1; d < 32; d <<= 1) {
            int y = __shfl_up_sync(0xFFFFFFFFu, xs, d);
            if (lane >= d) xs += y;
        }
        wsum[lane] = xs - s;  // exclusive warp offsets
    }
    __syncthreads();
    int excl = x - v + wsum[w];
    if (gid < n) g_rowstart[gid] = excl;
    if (t == 1023) g_bsum[blockIdx.x] = excl + v;  // block total
}

// exclusive scan over up to 128 block sums (nb1k = 98)
__global__ void scan_sums_kernel(int nb) {
    __shared__ int ws[4];
    int t = threadIdx.x, lane = t & 31, w = t >> 5;
    int v = (t < nb) ? g_bsum[t] : 0;
    int x = v;
    #pragma unroll
    for (int d = 1; d < 32; d <<= 1) {
        int y = __shfl_up_sync(0xFFFFFFFFu, x, d);
        if (lane >= d) x += y;
    }
    if (lane == 31) ws[w] = x;
    __syncthreads();
    if (t == 0) {
        int a0 = ws[0], a1 = ws[1], a2 = ws[2];
        ws[3] = a0 + a1 + a2;  // exclusive offsets
        ws[2] = a0 + a1;
        ws[1] = a0;
        ws[0] = 0;
    }
    __syncthreads();
    if (t < nb) g_bsum[t] = x - v + ws[w];
}

__global__ void scan_finish_kernel(int n) {
    int i = blockIdx.x * 1024 + threadIdx.x;
    if (i < n) {
        int v = g_rowstart[i] + g_bsum[blockIdx.x];
        g_rowstart[i] = v;
        g_cursor[i] = v;
        int d = g_cnt_out[i];
        g_dinv[i] = 1.0f / (float)(d > 1 ? d : 1);
    }
}

__global__ void scatter_kernel(const int* __restrict__ ei, int E) {
    int e = blockIdx.x * blockDim.x + threadIdx.x;
    if (e < E) {
        int d = ei[E + e];
        int pos = atomicAdd(&g_cursor[d], 1);
        g_csr[pos] = ei[e];  // source ids grouped by dst
    }
}

// ---------------- tf32 mma.sync GEMM (persistent, 512 thr, double-buffered) ----------------
// out[M,N_] = A[M,128] @ W[128,N_]   (deg_inv applied later in agg)
// smem A: As[row][pos], stride SA=136 words, pos(k) = (k>>3)*8 + (k&3)*2 + ((k>>2)&1)
// smem B: Bs[((k>>3)*N_ + n)*8 + (k&3)*2 + ((k>>2)&1)]
#define SA 136

template <int N_, bool FIRST>
__global__ __launch_bounds__(512, 1)
void gemm_mma_kernel(const float* __restrict__ Ain, const float* __restrict__ W,
                     int M, int tile_lo, int tile_hi) {
    extern __shared__ uint32_t smem[];
    uint32_t* As = smem;                  // 128 * SA
    uint32_t* Bs = smem + 128 * SA;       // 128 * N_

    const float* __restrict__ A = FIRST ? Ain : g_hr;
    float* __restrict__ out = FIRST ? g_h1 : g_h2;

    constexpr int HALF = N_ / 2;
    constexpr int NT = HALF / 8;          // 8 for N=128, 4 for N=64
    const int tid = threadIdx.x;
    const int wid = tid >> 5;
    const int lane = tid & 31;
    const int qr = lane >> 2;
    const int qc = lane & 3;
    const int rg = wid & 7;               // row group (16 rows)
    const int cg = wid >> 3;              // col half

    // stage B once (tf32, permuted)
    for (int idx = tid; idx < 128 * N_; idx += 512) {
        int k = idx / N_;
        int n = idx - k * N_;
        Bs[(((k >> 3) * N_ + n) << 3) + ((k & 3) << 1) + ((k >> 2) & 1)] = cvt_tf32(W[idx]);
    }

    const int j2 = lane >> 1;             // k-block (8 wide) this lane-pair covers
    const int odd = lane & 1;

    float4 regs[8];
    int t = tile_lo + blockIdx.x;
    if (t < tile_hi) {
        #pragma unroll
        for (int it = 0; it < 8; it++) {
            int gr = t * 128 + wid + it * 16;
            regs[it] = (gr < M) ? *(const float4*)(A + (size_t)gr * 128 + lane * 4)
                                : make_float4(0.f, 0.f, 0.f, 0.f);
        }
    }
    __syncthreads();   // B staged (and harmless sync for all)

    for (; t < tile_hi; ) {
        // ---- STS: lane-pair exchange -> one conflict-free STS.128 per float4 ----
        #pragma unroll
        for (int it = 0; it < 8; it++) {
            int r = wid + it * 16;
            float4 v = regs[it];
            float ox = __shfl_xor_sync(0xFFFFFFFFu, v.x, 1);
            float oy = __shfl_xor_sync(0xFFFFFFFFu, v.y, 1);
            float oz = __shfl_xor_sync(0xFFFFFFFFu, v.z, 1);
            float ow = __shfl_xor_sync(0xFFFFFFFFu, v.w, 1);
            uint4 st;
            if (!odd) {      // positions 0..3 of k-block: {k0, k0+4, k0+1, k0+5}
                st.x = cvt_tf32(v.x); st.y = cvt_tf32(ox);
                st.z = cvt_tf32(v.y); st.w = cvt_tf32(oy);
            } else {         // positions 4..7: {k0+2, k0+6, k0+3, k0+7}
                st.x = cvt_tf32(oz); st.y = cvt_tf32(v.z);
                st.z = cvt_tf32(ow); st.w = cvt_tf32(v.w);
            }
            *(uint4*)(As + r * SA + j2 * 8 + odd * 4) = st;
        }
        __syncthreads();

        // ---- prefetch next tile into regs (overlaps with compute) ----
        int tn = t + gridDim.x;
        if (tn < tile_hi) {
            #pragma unroll
            for (int it = 0; it < 8; it++) {
                int gr = tn * 128 + wid + it * 16;
                regs[it] = (gr < M) ? *(const float4*)(A + (size_t)gr * 128 + lane * 4)
                                    : make_float4(0.f, 0.f, 0.f, 0.f);
            }
        }

        // ---- compute ----
        float acc[NT][4];
        #pragma unroll
        for (int nt = 0; nt < NT; nt++)
            #pragma unroll
            for (int j = 0; j < 4; j++) acc[nt][j] = 0.f;

        #pragma unroll
        for (int s = 0; s < 16; s++) {
            uint32_t a[4];
            const uint32_t* pa = As + (rg * 16 + qr) * SA + s * 8 + qc * 2;
            uint2 lo = *(const uint2*)pa;
            uint2 hi = *(const uint2*)(pa + 8 * SA);
            a[0] = lo.x; a[1] = hi.x; a[2] = lo.y; a[3] = hi.y;
            const uint32_t* pb = Bs + ((s * N_ + cg * HALF + qr) << 3) + qc * 2;
            #pragma unroll
            for (int nt = 0; nt < NT; nt++) {
                uint2 bb = *(const uint2*)(pb + (nt << 6));
                uint32_t b[2] = {bb.x, bb.y};
                mma_tf32(acc[nt], a, b);
            }
        }

        // ---- epilogue ----
        {
            int r0 = t * 128 + rg * 16 + qr;
            int r1 = r0 + 8;
            #pragma unroll
            for (int nt = 0; nt < NT; nt++) {
                int c = cg * HALF + nt * 8 + qc * 2;
                if (r0 < M)
                    *(float2*)(out + (size_t)r0 * N_ + c) = make_float2(acc[nt][0], acc[nt][1]);
                if (r1 < M)
                    *(float2*)(out + (size_t)r1 * N_ + c) = make_float2(acc[nt][2], acc[nt][3]);
            }
        }
        __syncthreads();
        t = tn;
    }
}

// ---------------- aggregation: warp per dst node, per-edge dinv fma ----------------
template <int C, bool FIRST>
__global__ void agg_kernel(const float* __restrict__ bias, float* __restrict__ outp,
                           int lo, int hi) {
    int gw = lo + ((blockIdx.x * blockDim.x + threadIdx.x) >> 5);
    int lane = threadIdx.x & 31;
    if (gw >= hi) return;

    const float* __restrict__ h = FIRST ? g_h1 : g_h2;
    float* __restrict__ out = FIRST ? g_hr : outp;

    int beg = g_rowstart[gw];
    int m = g_cnt_in[gw];

    if constexpr (C == 128) {
        size_t off = (size_t)lane * 4;
        float4 acc = make_float4(0.f, 0.f, 0.f, 0.f);
        int e = 0;
        for (; e + 2 <= m; e += 2) {
            int s0 = g_csr[beg + e];
            int s1 = g_csr[beg + e + 1];
            float d0 = __ldg(&g_dinv[s0]);
            float d1 = __ldg(&g_dinv[s1]);
            float4 a = *(const float4*)(h + (size_t)s0 * C + off);
            float4 b = *(const float4*)(h + (size_t)s1 * C + off);
            acc.x = fmaf(a.x, d0, fmaf(b.x, d1, acc.x));
            acc.y = fmaf(a.y, d0, fmaf(b.y, d1, acc.y));
            acc.z = fmaf(a.z, d0, fmaf(b.z, d1, acc.z));
            acc.w = fmaf(a.w, d0, fmaf(b.w, d1, acc.w));
        }
        if (e < m) {
            int s = g_csr[beg + e];
            float d = __ldg(&g_dinv[s]);
            float4 a = *(const float4*)(h + (size_t)s * C + off);
            acc.x = fmaf(a.x, d, acc.x); acc.y = fmaf(a.y, d, acc.y);
            acc.z = fmaf(a.z, d, acc.z); acc.w = fmaf(a.w, d, acc.w);
        }
        float4 bb = *(const float4*)(bias + lane * 4);
        acc.x += bb.x; acc.y += bb.y; acc.z += bb.z; acc.w += bb.w;
        if (FIRST) {
            acc.x = fmaxf(acc.x, 0.f); acc.y = fmaxf(acc.y, 0.f);
            acc.z = fmaxf(acc.z, 0.f); acc.w = fmaxf(acc.w, 0.f);
        }
        *(float4*)(out + (size_t)gw * C + off) = acc;
    } else {
        size_t off = (size_t)lane * 2;
        float2 acc = make_float2(0.f, 0.f);
        int e = 0;
        for (; e + 2 <= m; e += 2) {
            int s0 = g_csr[beg + e];
            int s1 = g_csr[beg + e + 1];
            float d0 = __ldg(&g_dinv[s0]);
            float d1 = __ldg(&g_dinv[s1]);
            float2 a = *(const float2*)(h + (size_t)s0 * C + off);
            float2 b = *(const float2*)(h + (size_t)s1 * C + off);
            acc.x = fmaf(a.x, d0, fmaf(b.x, d1, acc.x));
            acc.y = fmaf(a.y, d0, fmaf(b.y, d1, acc.y));
        }
        if (e < m) {
            int s = g_csr[beg + e];
            float d = __ldg(&g_dinv[s]);
            float2 a = *(const float2*)(h + (size_t)s * C + off);
            acc.x = fmaf(a.x, d, acc.x); acc.y = fmaf(a.y, d, acc.y);
        }
        float2 bb = *(const float2*)(bias + lane * 2);
        acc.x += bb.x; acc.y += bb.y;
        if (FIRST) { acc.x = fmaxf(acc.x, 0.f); acc.y = fmaxf(acc.y, 0.f); }
        *(float2*)(out + (size_t)gw * C + off) = acc;
    }
}

// ---------------- launch ----------------
extern "C" void kernel_launch(void* const* d_in, const int* in_sizes, int n_in,
                              void* d_out, int out_size) {
    const float* x  = (const float*)d_in[0];
    const int*   ei = (const int*)d_in[1];
    const float* W1 = (const float*)d_in[2];
    const float* b1 = (const float*)d_in[3];
    const float* W2 = (const float*)d_in[4];
    const float* b2 = (const float*)d_in[5];
    float* out = (float*)d_out;

    int N = in_sizes[0] / INC;   // 100000
    int E = in_sizes[1] / 2;     // 1600000

    int nb1k = (N + 1023) / 1024;
    int n_tiles = (N + 127) / 128;
    int half_tiles = n_tiles / 2;
    int halfN = half_tiles * 128;

    const int SMEM1 = (128 * SA + 128 * HIDC) * 4;   // ~132KB
    const int SMEM2 = (128 * SA + 128 * OUTC) * 4;   // ~100KB

    static int sm_count = 0;
    static cudaStream_t s2 = nullptr;
    static cudaEvent_t evFork = nullptr, evCsr = nullptr, evG1 = nullptr,
                       evA1a = nullptr, evA1b = nullptr;
    static bool init_ok = false;
    if (!init_ok) {
        int dev = 0, c = 0;
        cudaGetDevice(&dev);
        if (cudaDeviceGetAttribute(&c, cudaDevAttrMultiProcessorCount, dev) != cudaSuccess || c <= 0)
            c = 148;
        sm_count = c;
        cudaFuncSetAttribute(gemm_mma_kernel<HIDC, true>,
                             cudaFuncAttributeMaxDynamicSharedMemorySize, SMEM1);
        cudaFuncSetAttribute(gemm_mma_kernel<OUTC, false>,
                             cudaFuncAttributeMaxDynamicSharedMemorySize, SMEM2);
        cudaStreamCreateWithFlags(&s2, cudaStreamNonBlocking);
        cudaEventCreateWithFlags(&evFork, cudaEventDisableTiming);
        cudaEventCreateWithFlags(&evCsr,  cudaEventDisableTiming);
        cudaEventCreateWithFlags(&evG1,   cudaEventDisableTiming);
        cudaEventCreateWithFlags(&evA1a,  cudaEventDisableTiming);
        cudaEventCreateWithFlags(&evA1b,  cudaEventDisableTiming);
        init_ok = true;
    }

    // ---- fork: CSR chain on s2, GEMM1 on main ----
    cudaEventRecord(evFork, 0);
    cudaStreamWaitEvent(s2, evFork, 0);

    zero_kernel<<<(N + 255) / 256, 256, 0, s2>>>(N);
    hist_kernel<<<(E + 255) / 256, 256, 0, s2>>>(ei, E);
    scan_block_kernel<<<nb1k, 1024, 0, s2>>>(N);
    scan_sums_kernel<<<1, 128, 0, s2>>>(nb1k);
    scan_finish_kernel<<<nb1k, 1024, 0, s2>>>(N);
    scatter_kernel<<<(E + 255) / 256, 256, 0, s2>>>(ei, E);
    cudaEventRecord(evCsr, s2);

    gemm_mma_kernel<HIDC, true><<<sm_count, 512, SMEM1, 0>>>(x, W1, N, 0, n_tiles);
    cudaEventRecord(evG1, 0);

    // ---- join, then agg1 split: half A on main, half B on s2 (staggered) ----
    cudaStreamWaitEvent(0, evCsr, 0);
    {
        int nodes = halfN;
        agg_kernel<HIDC, true><<<((size_t)nodes * 32 + 255) / 256, 256, 0, 0>>>(b1, nullptr, 0, halfN);
    }
    cudaEventRecord(evA1a, 0);

    cudaStreamWaitEvent(s2, evG1, 0);
    cudaStreamWaitEvent(s2, evA1a, 0);
    {
        int nodes = N - halfN;
        agg_kernel<HIDC, true><<<((size_t)nodes * 32 + 255) / 256, 256, 0, s2>>>(b1, nullptr, halfN, N);
    }
    cudaEventRecord(evA1b, s2);

    // ---- gemm2 half A overlaps agg1 half B ----
    gemm_mma_kernel<OUTC, false><<<sm_count, 512, SMEM2, 0>>>(nullptr, W2, N, 0, half_tiles);
    cudaStreamWaitEvent(0, evA1b, 0);
    gemm_mma_kernel<OUTC, false><<<sm_count, 512, SMEM2, 0>>>(nullptr, W2, N, half_tiles, n_tiles);

    // ---- final aggregation ----
    agg_kernel<OUTC, false><<<((size_t)N * 32 + 255) / 256, 256, 0, 0>>>(b2, out, 0, N);
}

// round 5
// speedup vs baseline: 1.1521x; 1.1521x over previous
#include <cuda_runtime.h>
#include <cuda_fp16.h>
#include <cstdint>

// Problem shape (fixed by the dataset)
#define NMAX 100000
#define EMAX 1600000
#define INC 128
#define HIDC 128
#define OUTC 64

// ---------------- scratch (no allocation allowed) ----------------
__device__ __half g_h1[(size_t)NMAX * HIDC];  // x@W1 (unscaled, fp16)
__device__ float  g_hr[(size_t)NMAX * HIDC];  // relu(agg1 + b1), fp32
__device__ __half g_h2[(size_t)NMAX * OUTC];  // hr@W2 (unscaled, fp16)
__device__ float  g_dinv[NMAX];
__device__ int    g_cnt_in[NMAX];
__device__ int    g_cnt_out[NMAX];
__device__ int    g_rowstart[NMAX];
__device__ int    g_cursor[NMAX];
__device__ int    g_total;
__device__ int    g_csr[EMAX];

// ---------------- helpers ----------------
__device__ __forceinline__ uint32_t cvt_tf32(float f) {
    uint32_t r;
    asm("cvt.rna.tf32.f32 %0, %1;" : "=r"(r) : "f"(f));
    return r;
}

__device__ __forceinline__ void mma_tf32(float* c, const uint32_t* a, const uint32_t* b) {
    asm volatile(
        "mma.sync.aligned.m16n8k8.row.col.f32.tf32.tf32.f32 "
        "{%0,%1,%2,%3}, {%4,%5,%6,%7}, {%8,%9}, {%0,%1,%2,%3};"
        : "+f"(c[0]), "+f"(c[1]), "+f"(c[2]), "+f"(c[3])
        : "r"(a[0]), "r"(a[1]), "r"(a[2]), "r"(a[3]), "r"(b[0]), "r"(b[1]));
}

// ---------------- CSR build ----------------
__global__ void zero_kernel(int n) {
    int i = blockIdx.x * blockDim.x + threadIdx.x;
    if (i < n) { g_cnt_in[i] = 0; g_cnt_out[i] = 0; }
    if (i == 0) g_total = 0;
}

__global__ void hist_kernel(const int* __restrict__ ei, int E) {
    int e = blockIdx.x * blockDim.x + threadIdx.x;
    if (e < E) {
        atomicAdd(&g_cnt_out[ei[e]], 1);      // src -> out-degree (normalization)
        atomicAdd(&g_cnt_in[ei[E + e]], 1);   // dst -> in-degree (CSR)
    }
}

// Fused scan: block-local shuffle scan + one atomic segment allocation per block.
// CSR segments need to be disjoint, not ordered by node id.
__global__ void alloc_scan_kernel(int n) {
    __shared__ int wsum[32];
    __shared__ int sbase;
    int t = threadIdx.x, lane = t & 31, w = t >> 5;
    int gid = blockIdx.x * 1024 + t;
    int v = (gid < n) ? g_cnt_in[gid] : 0;
    int x = v;
    #pragma unroll
    for (int d = 1; d < 32; d <<= 1) {
        int y = __shfl_up_sync(0xFFFFFFFFu, x, d);
        if (lane >= d) x += y;
    }
    if (lane == 31) wsum[w] = x;
    __syncthreads();
    if (w == 0) {
        int s = wsum[lane];
        int xs = s;
        #pragma unroll
        for (int d = 1; d < 32; d <<= 1) {
            int y = __shfl_up_sync(0xFFFFFFFFu, xs, d);
            if (lane >= d) xs += y;
        }
        wsum[lane] = xs - s;  // exclusive warp offsets
    }
    __syncthreads();
    int excl = x - v + wsum[w];
    if (t == 1023) sbase = atomicAdd(&g_total, excl + v);
    __syncthreads();
    if (gid < n) {
        int base = sbase + excl;
        g_rowstart[gid] = base;
        g_cursor[gid] = base;
        int d = g_cnt_out[gid];
        g_dinv[gid] = 1.0f / (float)(d > 1 ? d : 1);
    }
}

__global__ void scatter_kernel(const int* __restrict__ ei, int E) {
    int e = blockIdx.x * blockDim.x + threadIdx.x;
    if (e < E) {
        int d = ei[E + e];
        int pos = atomicAdd(&g_cursor[d], 1);
        g_csr[pos] = ei[e];  // source ids grouped by dst
    }
}

// ---------------- tf32 mma.sync GEMM (persistent, 512 thr, double-buffered) ----------------
// out_fp16[M,N_] = A[M,128] @ W[128,N_]   (deg_inv applied later in agg)
// smem A: As[row][pos], stride SA=136 words, pos(k) = (k>>3)*8 + (k&3)*2 + ((k>>2)&1)
// smem B: Bs[((k>>3)*N_ + n)*8 + (k&3)*2 + ((k>>2)&1)]
#define SA 136

template <int N_, bool FIRST>
__global__ __launch_bounds__(512, 1)
void gemm_mma_kernel(const float* __restrict__ Ain, const float* __restrict__ W,
                     int M, int n_tiles) {
    extern __shared__ uint32_t smem[];
    uint32_t* As = smem;                  // 128 * SA
    uint32_t* Bs = smem + 128 * SA;       // 128 * N_

    const float* __restrict__ A = FIRST ? Ain : g_hr;
    __half* __restrict__ out = FIRST ? g_h1 : g_h2;

    constexpr int HALF = N_ / 2;
    constexpr int NT = HALF / 8;          // 8 for N=128, 4 for N=64
    const int tid = threadIdx.x;
    const int wid = tid >> 5;
    const int lane = tid & 31;
    const int qr = lane >> 2;
    const int qc = lane & 3;
    const int rg = wid & 7;               // row group (16 rows)
    const int cg = wid >> 3;              // col half

    // stage B once (tf32, permuted)
    for (int idx = tid; idx < 128 * N_; idx += 512) {
        int k = idx / N_;
        int n = idx - k * N_;
        Bs[(((k >> 3) * N_ + n) << 3) + ((k & 3) << 1) + ((k >> 2) & 1)] = cvt_tf32(W[idx]);
    }

    const int j2 = lane >> 1;             // k-block (8 wide) this lane-pair covers
    const int odd = lane & 1;

    float4 regs[8];
    int t = blockIdx.x;
    if (t < n_tiles) {
        #pragma unroll
        for (int it = 0; it < 8; it++) {
            int gr = t * 128 + wid + it * 16;
            regs[it] = (gr < M) ? *(const float4*)(A + (size_t)gr * 128 + lane * 4)
                                : make_float4(0.f, 0.f, 0.f, 0.f);
        }
    }
    __syncthreads();   // B staged

    for (; t < n_tiles; ) {
        // ---- STS: lane-pair exchange -> conflict-free STS.128 ----
        #pragma unroll
        for (int it = 0; it < 8; it++) {
            int r = wid + it * 16;
            float4 v = regs[it];
            float ox = __shfl_xor_sync(0xFFFFFFFFu, v.x, 1);
            float oy = __shfl_xor_sync(0xFFFFFFFFu, v.y, 1);
            float oz = __shfl_xor_sync(0xFFFFFFFFu, v.z, 1);
            float ow = __shfl_xor_sync(0xFFFFFFFFu, v.w, 1);
            uint4 st;
            if (!odd) {
                st.x = cvt_tf32(v.x); st.y = cvt_tf32(ox);
                st.z = cvt_tf32(v.y); st.w = cvt_tf32(oy);
            } else {
                st.x = cvt_tf32(oz); st.y = cvt_tf32(v.z);
                st.z = cvt_tf32(ow); st.w = cvt_tf32(v.w);
            }
            *(uint4*)(As + r * SA + j2 * 8 + odd * 4) = st;
        }
        __syncthreads();

        // ---- prefetch next tile (overlaps compute) ----
        int tn = t + gridDim.x;
        if (tn < n_tiles) {
            #pragma unroll
            for (int it = 0; it < 8; it++) {
                int gr = tn * 128 + wid + it * 16;
                regs[it] = (gr < M) ? *(const float4*)(A + (size_t)gr * 128 + lane * 4)
                                    : make_float4(0.f, 0.f, 0.f, 0.f);
            }
        }

        // ---- compute ----
        float acc[NT][4];
        #pragma unroll
        for (int nt = 0; nt < NT; nt++)
            #pragma unroll
            for (int j = 0; j < 4; j++) acc[nt][j] = 0.f;

        #pragma unroll
        for (int s = 0; s < 16; s++) {
            uint32_t a[4];
            const uint32_t* pa = As + (rg * 16 + qr) * SA + s * 8 + qc * 2;
            uint2 lo = *(const uint2*)pa;
            uint2 hi = *(const uint2*)(pa + 8 * SA);
            a[0] = lo.x; a[1] = hi.x; a[2] = lo.y; a[3] = hi.y;
            const uint32_t* pb = Bs + ((s * N_ + cg * HALF + qr) << 3) + qc * 2;
            #pragma unroll
            for (int nt = 0; nt < NT; nt++) {
                uint2 bb = *(const uint2*)(pb + (nt << 6));
                uint32_t b[2] = {bb.x, bb.y};
                mma_tf32(acc[nt], a, b);
            }
        }

        // ---- epilogue: fp16 store ----
        {
            int r0 = t * 128 + rg * 16 + qr;
            int r1 = r0 + 8;
            #pragma unroll
            for (int nt = 0; nt < NT; nt++) {
                int c = cg * HALF + nt * 8 + qc * 2;
                if (r0 < M)
                    *(__half2*)(out + (size_t)r0 * N_ + c) = __floats2half2_rn(acc[nt][0], acc[nt][1]);
                if (r1 < M)
                    *(__half2*)(out + (size_t)r1 * N_ + c) = __floats2half2_rn(acc[nt][2], acc[nt][3]);
            }
        }
        __syncthreads();
        t = tn;
    }
}

// ---------------- aggregation: warp per dst node, fp16 gather, fp32 accumulate ----------------
template <int C, bool FIRST>
__global__ void agg_kernel(const float* __restrict__ bias, float* __restrict__ outp, int n) {
    int gw = (blockIdx.x * blockDim.x + threadIdx.x) >> 5;
    int lane = threadIdx.x & 31;
    if (gw >= n) return;

    const __half* __restrict__ h = FIRST ? g_h1 : g_h2;
    float* __restrict__ out = FIRST ? g_hr : outp;

    int beg = g_rowstart[gw];
    int m = g_cnt_in[gw];

    if constexpr (C == 128) {
        // lane covers 4 channels: 8 bytes (uint2) per row
        size_t off = (size_t)lane * 4;
        float4 acc = make_float4(0.f, 0.f, 0.f, 0.f);
        int e = 0;
        for (; e + 2 <= m; e += 2) {
            int s0 = g_csr[beg + e];
            int s1 = g_csr[beg + e + 1];
            float d0 = __ldg(&g_dinv[s0]);
            float d1 = __ldg(&g_dinv[s1]);
            uint2 u0 = *(const uint2*)(h + (size_t)s0 * C + off);
            uint2 u1 = *(const uint2*)(h + (size_t)s1 * C + off);
            float2 a0 = __half22float2(*reinterpret_cast<__half2*>(&u0.x));
            float2 a1 = __half22float2(*reinterpret_cast<__half2*>(&u0.y));
            float2 b0 = __half22float2(*reinterpret_cast<__half2*>(&u1.x));
            float2 b1 = __half22float2(*reinterpret_cast<__half2*>(&u1.y));
            acc.x = fmaf(a0.x, d0, fmaf(b0.x, d1, acc.x));
            acc.y = fmaf(a0.y, d0, fmaf(b0.y, d1, acc.y));
            acc.z = fmaf(a1.x, d0, fmaf(b1.x, d1, acc.z));
            acc.w = fmaf(a1.y, d0, fmaf(b1.y, d1, acc.w));
        }
        if (e < m) {
            int s = g_csr[beg + e];
            float d = __ldg(&g_dinv[s]);
            uint2 u = *(const uint2*)(h + (size_t)s * C + off);
            float2 a0 = __half22float2(*reinterpret_cast<__half2*>(&u.x));
            float2 a1 = __half22float2(*reinterpret_cast<__half2*>(&u.y));
            acc.x = fmaf(a0.x, d, acc.x); acc.y = fmaf(a0.y, d, acc.y);
            acc.z = fmaf(a1.x, d, acc.z); acc.w = fmaf(a1.y, d, acc.w);
        }
        float4 bb = *(const float4*)(bias + lane * 4);
        acc.x += bb.x; acc.y += bb.y; acc.z += bb.z; acc.w += bb.w;
        if (FIRST) {
            acc.x = fmaxf(acc.x, 0.f); acc.y = fmaxf(acc.y, 0.f);
            acc.z = fmaxf(acc.z, 0.f); acc.w = fmaxf(acc.w, 0.f);
        }
        *(float4*)(out + (size_t)gw * C + off) = acc;
    } else {
        // lane covers 2 channels: 4 bytes (uint) per row
        size_t off = (size_t)lane * 2;
        float2 acc = make_float2(0.f, 0.f);
        int e = 0;
        for (; e + 2 <= m; e += 2) {
            int s0 = g_csr[beg + e];
            int s1 = g_csr[beg + e + 1];
            float d0 = __ldg(&g_dinv[s0]);
            float d1 = __ldg(&g_dinv[s1]);
            uint32_t u0 = *(const uint32_t*)(h + (size_t)s0 * C + off);
            uint32_t u1 = *(const uint32_t*)(h + (size_t)s1 * C + off);
            float2 a = __half22float2(*reinterpret_cast<__half2*>(&u0));
            float2 b = __half22float2(*reinterpret_cast<__half2*>(&u1));
            acc.x = fmaf(a.x, d0, fmaf(b.x, d1, acc.x));
            acc.y = fmaf(a.y, d0, fmaf(b.y, d1, acc.y));
        }
        if (e < m) {
            int s = g_csr[beg + e];
            float d = __ldg(&g_dinv[s]);
            uint32_t u = *(const uint32_t*)(h + (size_t)s * C + off);
            float2 a = __half22float2(*reinterpret_cast<__half2*>(&u));
            acc.x = fmaf(a.x, d, acc.x); acc.y = fmaf(a.y, d, acc.y);
        }
        float2 bb = *(const float2*)(bias + lane * 2);
        acc.x += bb.x; acc.y += bb.y;
        if (FIRST) { acc.x = fmaxf(acc.x, 0.f); acc.y = fmaxf(acc.y, 0.f); }
        *(float2*)(out + (size_t)gw * C + off) = acc;
    }
}

// ---------------- launch ----------------
extern "C" void kernel_launch(void* const* d_in, const int* in_sizes, int n_in,
                              void* d_out, int out_size) {
    const float* x  = (const float*)d_in[0];
    const int*   ei = (const int*)d_in[1];
    const float* W1 = (const float*)d_in[2];
    const float* b1 = (const float*)d_in[3];
    const float* W2 = (const float*)d_in[4];
    const float* b2 = (const float*)d_in[5];
    float* out = (float*)d_out;

    int N = in_sizes[0] / INC;   // 100000
    int E = in_sizes[1] / 2;     // 1600000

    int nb1k = (N + 1023) / 1024;
    int n_tiles = (N + 127) / 128;

    const int SMEM1 = (128 * SA + 128 * HIDC) * 4;   // ~132KB
    const int SMEM2 = (128 * SA + 128 * OUTC) * 4;   // ~100KB

    static int sm_count = 0;
    static cudaStream_t s2 = nullptr;
    static cudaEvent_t evFork = nullptr, evCsr = nullptr;
    static bool init_ok = false;
    if (!init_ok) {
        int dev = 0, c = 0;
        cudaGetDevice(&dev);
        if (cudaDeviceGetAttribute(&c, cudaDevAttrMultiProcessorCount, dev) != cudaSuccess || c <= 0)
            c = 148;
        sm_count = c;
        cudaFuncSetAttribute(gemm_mma_kernel<HIDC, true>,
                             cudaFuncAttributeMaxDynamicSharedMemorySize, SMEM1);
        cudaFuncSetAttribute(gemm_mma_kernel<OUTC, false>,
                             cudaFuncAttributeMaxDynamicSharedMemorySize, SMEM2);
        cudaStreamCreateWithFlags(&s2, cudaStreamNonBlocking);
        cudaEventCreateWithFlags(&evFork, cudaEventDisableTiming);
        cudaEventCreateWithFlags(&evCsr,  cudaEventDisableTiming);
        init_ok = true;
    }

    // ---- fork: CSR chain on s2 (atomics/latency-bound), GEMM1 on main (DRAM/tensor) ----
    cudaEventRecord(evFork, 0);
    cudaStreamWaitEvent(s2, evFork, 0);

    zero_kernel<<<(N + 255) / 256, 256, 0, s2>>>(N);
    hist_kernel<<<(E + 255) / 256, 256, 0, s2>>>(ei, E);
    alloc_scan_kernel<<<nb1k, 1024, 0, s2>>>(N);
    scatter_kernel<<<(E + 255) / 256, 256, 0, s2>>>(ei, E);
    cudaEventRecord(evCsr, s2);

    gemm_mma_kernel<HIDC, true><<<sm_count, 512, SMEM1, 0>>>(x, W1, N, n_tiles);

    // ---- join, then serial memory-bound tail (overlap doesn't help LTS-bound phases) ----
    cudaStreamWaitEvent(0, evCsr, 0);
    agg_kernel<HIDC, true><<<((size_t)N * 32 + 255) / 256, 256, 0, 0>>>(b1, nullptr, N);
    gemm_mma_kernel<OUTC, false><<<sm_count, 512, SMEM2, 0>>>(nullptr, W2, N, n_tiles);
    agg_kernel<OUTC, false><<<((size_t)N * 32 + 255) / 256, 256, 0, 0>>>(b2, out, N);
}

// round 6
// speedup vs baseline: 1.1961x; 1.0382x over previous
#include <cuda_runtime.h>
#include <cuda_fp16.h>
#include <cstdint>

// Problem shape (fixed by the dataset)
#define NMAX 100000
#define EMAX 1600000
#define INC 128
#define HIDC 128
#define OUTC 64

// ---------------- scratch (no allocation allowed) ----------------
__device__ __half g_h1[(size_t)NMAX * HIDC];  // x@W1 (unscaled, fp16)
__device__ __half g_hr[(size_t)NMAX * HIDC];  // relu(agg1 + b1), fp16
__device__ __half g_h2[(size_t)NMAX * OUTC];  // hr@W2 (unscaled, fp16)
__device__ float  g_dinv[NMAX];
__device__ int    g_cnt_in[NMAX];
__device__ int    g_cnt_out[NMAX];
__device__ int    g_rowstart[NMAX];
__device__ int    g_cursor[NMAX];
__device__ int    g_total;
__device__ int    g_csr[EMAX];

// ---------------- helpers ----------------
__device__ __forceinline__ uint32_t cvt_tf32(float f) {
    uint32_t r;
    asm("cvt.rna.tf32.f32 %0, %1;" : "=r"(r) : "f"(f));
    return r;
}

__device__ __forceinline__ void mma_tf32(float* c, const uint32_t* a, const uint32_t* b) {
    asm volatile(
        "mma.sync.aligned.m16n8k8.row.col.f32.tf32.tf32.f32 "
        "{%0,%1,%2,%3}, {%4,%5,%6,%7}, {%8,%9}, {%0,%1,%2,%3};"
        : "+f"(c[0]), "+f"(c[1]), "+f"(c[2]), "+f"(c[3])
        : "r"(a[0]), "r"(a[1]), "r"(a[2]), "r"(a[3]), "r"(b[0]), "r"(b[1]));
}

// ---------------- CSR build ----------------
__global__ void hist_kernel(const int* __restrict__ ei, int E) {
    int e = blockIdx.x * blockDim.x + threadIdx.x;
    if (e < E) {
        atomicAdd(&g_cnt_out[ei[e]], 1);      // src -> out-degree (normalization)
        atomicAdd(&g_cnt_in[ei[E + e]], 1);   // dst -> in-degree (CSR)
    }
}

// Fused scan: block-local shuffle scan + one atomic segment allocation per block.
// CSR segments need to be disjoint, not ordered by node id.
__global__ void alloc_scan_kernel(int n) {
    __shared__ int wsum[32];
    __shared__ int sbase;
    int t = threadIdx.x, lane = t & 31, w = t >> 5;
    int gid = blockIdx.x * 1024 + t;
    int v = (gid < n) ? g_cnt_in[gid] : 0;
    int x = v;
    #pragma unroll
    for (int d = 1; d < 32; d <<= 1) {
        int y = __shfl_up_sync(0xFFFFFFFFu, x, d);
        if (lane >= d) x += y;
    }
    if (lane == 31) wsum[w] = x;
    __syncthreads();
    if (w == 0) {
        int s = wsum[lane];
        int xs = s;
        #pragma unroll
        for (int d = 1; d < 32; d <<= 1) {
            int y = __shfl_up_sync(0xFFFFFFFFu, xs, d);
            if (lane >= d) xs += y;
        }
        wsum[lane] = xs - s;  // exclusive warp offsets
    }
    __syncthreads();
    int excl = x - v + wsum[w];
    if (t == 1023) sbase = atomicAdd(&g_total, excl + v);
    __syncthreads();
    if (gid < n) {
        int base = sbase + excl;
        g_rowstart[gid] = base;
        g_cursor[gid] = base;
        int d = g_cnt_out[gid];
        g_dinv[gid] = 1.0f / (float)(d > 1 ? d : 1);
    }
}

__global__ void scatter_kernel(const int* __restrict__ ei, int E) {
    int e = blockIdx.x * blockDim.x + threadIdx.x;
    if (e < E) {
        int d = ei[E + e];
        int pos = atomicAdd(&g_cursor[d], 1);
        g_csr[pos] = ei[e];  // source ids grouped by dst
    }
}

// ---------------- tf32 mma.sync GEMM (persistent, 512 thr, double-buffered) ----------------
// out_fp16[M,N_] = A[M,128] @ W[128,N_]   (deg_inv applied later in agg)
// smem A: As[row][pos], stride SA=136 words, pos(k) = (k>>3)*8 + (k&3)*2 + ((k>>2)&1)
// smem B: Bs[((k>>3)*N_ + n)*8 + (k&3)*2 + ((k>>2)&1)]
#define SA 136

template <int N_, bool FIRST>
__global__ __launch_bounds__(512, 1)
void gemm_mma_kernel(const float* __restrict__ Ain, const float* __restrict__ W,
                     int M, int n_tiles) {
    extern __shared__ uint32_t smem[];
    uint32_t* As = smem;                  // 128 * SA
    uint32_t* Bs = smem + 128 * SA;       // 128 * N_

    __half* __restrict__ out = FIRST ? g_h1 : g_h2;

    constexpr int HALF = N_ / 2;
    constexpr int NT = HALF / 8;          // 8 for N=128, 4 for N=64
    const int tid = threadIdx.x;
    const int wid = tid >> 5;
    const int lane = tid & 31;
    const int qr = lane >> 2;
    const int qc = lane & 3;
    const int rg = wid & 7;               // row group (16 rows)
    const int cg = wid >> 3;              // col half

    // stage B once (tf32, permuted)
    for (int idx = tid; idx < 128 * N_; idx += 512) {
        int k = idx / N_;
        int n = idx - k * N_;
        Bs[(((k >> 3) * N_ + n) << 3) + ((k & 3) << 1) + ((k >> 2) & 1)] = cvt_tf32(W[idx]);
    }

    const int j2 = lane >> 1;             // k-block (8 wide) this lane-pair covers
    const int odd = lane & 1;

    // per-iteration tile load: 4 channels per lane (row = 128 ch)
    auto load_row = [&](int gr) -> float4 {
        if (gr >= M) return make_float4(0.f, 0.f, 0.f, 0.f);
        if constexpr (FIRST) {
            return *(const float4*)(Ain + (size_t)gr * 128 + lane * 4);
        } else {
            uint2 u = *(const uint2*)(g_hr + (size_t)gr * 128 + lane * 4);
            float2 a = __half22float2(*reinterpret_cast<__half2*>(&u.x));
            float2 b = __half22float2(*reinterpret_cast<__half2*>(&u.y));
            return make_float4(a.x, a.y, b.x, b.y);
        }
    };

    float4 regs[8];
    int t = blockIdx.x;
    if (t < n_tiles) {
        #pragma unroll
        for (int it = 0; it < 8; it++)
            regs[it] = load_row(t * 128 + wid + it * 16);
    }
    __syncthreads();   // B staged

    for (; t < n_tiles; ) {
        // ---- STS: lane-pair exchange -> conflict-free STS.128 ----
        #pragma unroll
        for (int it = 0; it < 8; it++) {
            int r = wid + it * 16;
            float4 v = regs[it];
            float ox = __shfl_xor_sync(0xFFFFFFFFu, v.x, 1);
            float oy = __shfl_xor_sync(0xFFFFFFFFu, v.y, 1);
            float oz = __shfl_xor_sync(0xFFFFFFFFu, v.z, 1);
            float ow = __shfl_xor_sync(0xFFFFFFFFu, v.w, 1);
            uint4 st;
            if (!odd) {
                st.x = cvt_tf32(v.x); st.y = cvt_tf32(ox);
                st.z = cvt_tf32(v.y); st.w = cvt_tf32(oy);
            } else {
                st.x = cvt_tf32(oz); st.y = cvt_tf32(v.z);
                st.z = cvt_tf32(ow); st.w = cvt_tf32(v.w);
            }
            *(uint4*)(As + r * SA + j2 * 8 + odd * 4) = st;
        }
        __syncthreads();

        // ---- prefetch next tile (overlaps compute) ----
        int tn = t + gridDim.x;
        if (tn < n_tiles) {
            #pragma unroll
            for (int it = 0; it < 8; it++)
                regs[it] = load_row(tn * 128 + wid + it * 16);
        }

        // ---- compute ----
        float acc[NT][4];
        #pragma unroll
        for (int nt = 0; nt < NT; nt++)
            #pragma unroll
            for (int j = 0; j < 4; j++) acc[nt][j] = 0.f;

        #pragma unroll
        for (int s = 0; s < 16; s++) {
            uint32_t a[4];
            const uint32_t* pa = As + (rg * 16 + qr) * SA + s * 8 + qc * 2;
            uint2 lo = *(const uint2*)pa;
            uint2 hi = *(const uint2*)(pa + 8 * SA);
            a[0] = lo.x; a[1] = hi.x; a[2] = lo.y; a[3] = hi.y;
            const uint32_t* pb = Bs + ((s * N_ + cg * HALF + qr) << 3) + qc * 2;
            #pragma unroll
            for (int nt = 0; nt < NT; nt++) {
                uint2 bb = *(const uint2*)(pb + (nt << 6));
                uint32_t b[2] = {bb.x, bb.y};
                mma_tf32(acc[nt], a, b);
            }
        }

        // ---- epilogue: fp16 store ----
        {
            int r0 = t * 128 + rg * 16 + qr;
            int r1 = r0 + 8;
            #pragma unroll
            for (int nt = 0; nt < NT; nt++) {
                int c = cg * HALF + nt * 8 + qc * 2;
                if (r0 < M)
                    *(__half2*)(out + (size_t)r0 * N_ + c) = __floats2half2_rn(acc[nt][0], acc[nt][1]);
                if (r1 < M)
                    *(__half2*)(out + (size_t)r1 * N_ + c) = __floats2half2_rn(acc[nt][2], acc[nt][3]);
            }
        }
        __syncthreads();
        t = tn;
    }
}

// ---------------- aggregation: warp per dst node, 4-deep gather pipeline ----------------
// FIRST: out = relu(sum + b1) -> g_hr (fp16).  else: out = sum + b2 -> d_out (fp32)
template <int C, bool FIRST>
__global__ void agg_kernel(const float* __restrict__ bias, float* __restrict__ outp, int n) {
    int gw = (blockIdx.x * blockDim.x + threadIdx.x) >> 5;
    int lane = threadIdx.x & 31;
    if (gw >= n) return;

    const __half* __restrict__ h = FIRST ? g_h1 : g_h2;

    int beg = g_rowstart[gw];
    int m = g_cnt_in[gw];

    if constexpr (C == 128) {
        size_t off = (size_t)lane * 4;
        float4 acc = make_float4(0.f, 0.f, 0.f, 0.f);
        int e = 0;
        for (; e + 4 <= m; e += 4) {
            int s0 = g_csr[beg + e];
            int s1 = g_csr[beg + e + 1];
            int s2 = g_csr[beg + e + 2];
            int s3 = g_csr[beg + e + 3];
            uint2 u0 = *(const uint2*)(h + (size_t)s0 * C + off);
            uint2 u1 = *(const uint2*)(h + (size_t)s1 * C + off);
            uint2 u2 = *(const uint2*)(h + (size_t)s2 * C + off);
            uint2 u3 = *(const uint2*)(h + (size_t)s3 * C + off);
            float d0 = __ldg(&g_dinv[s0]);
            float d1 = __ldg(&g_dinv[s1]);
            float d2 = __ldg(&g_dinv[s2]);
            float d3 = __ldg(&g_dinv[s3]);
            float2 a0 = __half22float2(*reinterpret_cast<__half2*>(&u0.x));
            float2 a1 = __half22float2(*reinterpret_cast<__half2*>(&u0.y));
            float2 b0 = __half22float2(*reinterpret_cast<__half2*>(&u1.x));
            float2 b1v = __half22float2(*reinterpret_cast<__half2*>(&u1.y));
            float2 c0 = __half22float2(*reinterpret_cast<__half2*>(&u2.x));
            float2 c1 = __half22float2(*reinterpret_cast<__half2*>(&u2.y));
            float2 e0 = __half22float2(*reinterpret_cast<__half2*>(&u3.x));
            float2 e1 = __half22float2(*reinterpret_cast<__half2*>(&u3.y));
            acc.x = fmaf(a0.x, d0, fmaf(b0.x, d1, fmaf(c0.x, d2, fmaf(e0.x, d3, acc.x))));
            acc.y = fmaf(a0.y, d0, fmaf(b0.y, d1, fmaf(c0.y, d2, fmaf(e0.y, d3, acc.y))));
            acc.z = fmaf(a1.x, d0, fmaf(b1v.x, d1, fmaf(c1.x, d2, fmaf(e1.x, d3, acc.z))));
            acc.w = fmaf(a1.y, d0, fmaf(b1v.y, d1, fmaf(c1.y, d2, fmaf(e1.y, d3, acc.w))));
        }
        for (; e < m; e++) {
            int s = g_csr[beg + e];
            float d = __ldg(&g_dinv[s]);
            uint2 u = *(const uint2*)(h + (size_t)s * C + off);
            float2 a0 = __half22float2(*reinterpret_cast<__half2*>(&u.x));
            float2 a1 = __half22float2(*reinterpret_cast<__half2*>(&u.y));
            acc.x = fmaf(a0.x, d, acc.x); acc.y = fmaf(a0.y, d, acc.y);
            acc.z = fmaf(a1.x, d, acc.z); acc.w = fmaf(a1.y, d, acc.w);
        }
        float4 bb = *(const float4*)(bias + lane * 4);
        acc.x += bb.x; acc.y += bb.y; acc.z += bb.z; acc.w += bb.w;
        if constexpr (FIRST) {
            acc.x = fmaxf(acc.x, 0.f); acc.y = fmaxf(acc.y, 0.f);
            acc.z = fmaxf(acc.z, 0.f); acc.w = fmaxf(acc.w, 0.f);
            uint2 st;
            *reinterpret_cast<__half2*>(&st.x) = __floats2half2_rn(acc.x, acc.y);
            *reinterpret_cast<__half2*>(&st.y) = __floats2half2_rn(acc.z, acc.w);
            *(uint2*)(g_hr + (size_t)gw * C + off) = st;
        } else {
            *(float4*)(outp + (size_t)gw * C + off) = acc;
        }
    } else {
        size_t off = (size_t)lane * 2;
        float2 acc = make_float2(0.f, 0.f);
        int e = 0;
        for (; e + 4 <= m; e += 4) {
            int s0 = g_csr[beg + e];
            int s1 = g_csr[beg + e + 1];
            int s2 = g_csr[beg + e + 2];
            int s3 = g_csr[beg + e + 3];
            uint32_t u0 = *(const uint32_t*)(h + (size_t)s0 * C + off);
            uint32_t u1 = *(const uint32_t*)(h + (size_t)s1 * C + off);
            uint32_t u2 = *(const uint32_t*)(h + (size_t)s2 * C + off);
            uint32_t u3 = *(const uint32_t*)(h + (size_t)s3 * C + off);
            float d0 = __ldg(&g_dinv[s0]);
            float d1 = __ldg(&g_dinv[s1]);
            float d2 = __ldg(&g_dinv[s2]);
            float d3 = __ldg(&g_dinv[s3]);
            float2 a = __half22float2(*reinterpret_cast<__half2*>(&u0));
            float2 b = __half22float2(*reinterpret_cast<__half2*>(&u1));
            float2 c = __half22float2(*reinterpret_cast<__half2*>(&u2));
            float2 f = __half22float2(*reinterpret_cast<__half2*>(&u3));
            acc.x = fmaf(a.x, d0, fmaf(b.x, d1, fmaf(c.x, d2, fmaf(f.x, d3, acc.x))));
            acc.y = fmaf(a.y, d0, fmaf(b.y, d1, fmaf(c.y, d2, fmaf(f.y, d3, acc.y))));
        }
        for (; e < m; e++) {
            int s = g_csr[beg + e];
            float d = __ldg(&g_dinv[s]);
            uint32_t u = *(const uint32_t*)(h + (size_t)s * C + off);
            float2 a = __half22float2(*reinterpret_cast<__half2*>(&u));
            acc.x = fmaf(a.x, d, acc.x); acc.y = fmaf(a.y, d, acc.y);
        }
        float2 bb = *(const float2*)(bias + lane * 2);
        acc.x += bb.x; acc.y += bb.y;
        *(float2*)(outp + (size_t)gw * C + off) = acc;
    }
}

// ---------------- launch ----------------
extern "C" void kernel_launch(void* const* d_in, const int* in_sizes, int n_in,
                              void* d_out, int out_size) {
    const float* x  = (const float*)d_in[0];
    const int*   ei = (const int*)d_in[1];
    const float* W1 = (const float*)d_in[2];
    const float* b1 = (const float*)d_in[3];
    const float* W2 = (const float*)d_in[4];
    const float* b2 = (const float*)d_in[5];
    float* out = (float*)d_out;

    int N = in_sizes[0] / INC;   // 100000
    int E = in_sizes[1] / 2;     // 1600000

    int nb1k = (N + 1023) / 1024;
    int n_tiles = (N + 127) / 128;

    const int SMEM1 = (128 * SA + 128 * HIDC) * 4;   // ~132KB
    const int SMEM2 = (128 * SA + 128 * OUTC) * 4;   // ~100KB

    static int sm_count = 0;
    static cudaStream_t s2 = nullptr;
    static cudaEvent_t evFork = nullptr, evCsr = nullptr;
    static void *p_cnt_in = nullptr, *p_cnt_out = nullptr, *p_total = nullptr;
    static bool init_ok = false;
    if (!init_ok) {
        int dev = 0, c = 0;
        cudaGetDevice(&dev);
        if (cudaDeviceGetAttribute(&c, cudaDevAttrMultiProcessorCount, dev) != cudaSuccess || c <= 0)
            c = 148;
        sm_count = c;
        cudaFuncSetAttribute(gemm_mma_kernel<HIDC, true>,
                             cudaFuncAttributeMaxDynamicSharedMemorySize, SMEM1);
        cudaFuncSetAttribute(gemm_mma_kernel<OUTC, false>,
                             cudaFuncAttributeMaxDynamicSharedMemorySize, SMEM2);
        cudaStreamCreateWithFlags(&s2, cudaStreamNonBlocking);
        cudaEventCreateWithFlags(&evFork, cudaEventDisableTiming);
        cudaEventCreateWithFlags(&evCsr,  cudaEventDisableTiming);
        cudaGetSymbolAddress(&p_cnt_in,  g_cnt_in);
        cudaGetSymbolAddress(&p_cnt_out, g_cnt_out);
        cudaGetSymbolAddress(&p_total,   g_total);
        init_ok = true;
    }

    // ---- fork: CSR chain on s2 (atomics/latency-bound), GEMM1 on main (DRAM/tensor) ----
    cudaEventRecord(evFork, 0);
    cudaStreamWaitEvent(s2, evFork, 0);

    cudaMemsetAsync(p_cnt_in,  0, (size_t)N * sizeof(int), s2);
    cudaMemsetAsync(p_cnt_out, 0, (size_t)N * sizeof(int), s2);
    cudaMemsetAsync(p_total,   0, sizeof(int), s2);
    hist_kernel<<<(E + 255) / 256, 256, 0, s2>>>(ei, E);
    alloc_scan_kernel<<<nb1k, 1024, 0, s2>>>(N);
    scatter_kernel<<<(E + 255) / 256, 256, 0, s2>>>(ei, E);
    cudaEventRecord(evCsr, s2);

    gemm_mma_kernel<HIDC, true><<<sm_count, 512, SMEM1, 0>>>(x, W1, N, n_tiles);

    // ---- join, then serial memory-bound tail ----
    cudaStreamWaitEvent(0, evCsr, 0);
    agg_kernel<HIDC, true><<<((size_t)N * 32 + 255) / 256, 256, 0, 0>>>(b1, nullptr, N);
    gemm_mma_kernel<OUTC, false><<<sm_count, 512, SMEM2, 0>>>(nullptr, W2, N, n_tiles);
    agg_kernel<OUTC, false><<<((size_t)N * 32 + 255) / 256, 256, 0, 0>>>(b2, out, N);
}

// round 7
// speedup vs baseline: 1.2238x; 1.0231x over previous
#include <cuda_runtime.h>
#include <cuda_fp16.h>
#include <cstdint>

// Problem shape (fixed by the dataset)
#define NMAX 100000
#define EMAX 1600000
#define INC 128
#define HIDC 128
#define OUTC 64

// ---------------- scratch (no allocation allowed) ----------------
__device__ __half g_h1[(size_t)NMAX * HIDC];  // x@W1 (unscaled, fp16)
__device__ __half g_hr[(size_t)NMAX * HIDC];  // relu(agg1 + b1), fp16
__device__ __half g_h2[(size_t)NMAX * OUTC];  // hr@W2 (unscaled, fp16)
__device__ float  g_dinv[NMAX];
__device__ int    g_cnt_in[NMAX];
__device__ int    g_cnt_out[NMAX];
__device__ int    g_rowstart[NMAX];
__device__ int    g_cursor[NMAX];
__device__ int    g_total;
__device__ int    g_csr[EMAX];

// ---------------- helpers ----------------
__device__ __forceinline__ uint32_t cvt_tf32(float f) {
    uint32_t r;
    asm("cvt.rna.tf32.f32 %0, %1;" : "=r"(r) : "f"(f));
    return r;
}

__device__ __forceinline__ void mma_tf32(float* c, const uint32_t* a, const uint32_t* b) {
    asm volatile(
        "mma.sync.aligned.m16n8k8.row.col.f32.tf32.tf32.f32 "
        "{%0,%1,%2,%3}, {%4,%5,%6,%7}, {%8,%9}, {%0,%1,%2,%3};"
        : "+f"(c[0]), "+f"(c[1]), "+f"(c[2]), "+f"(c[3])
        : "r"(a[0]), "r"(a[1]), "r"(a[2]), "r"(a[3]), "r"(b[0]), "r"(b[1]));
}

// ---------------- CSR build ----------------
__global__ void hist_kernel(const int* __restrict__ ei, int E) {
    int e = blockIdx.x * blockDim.x + threadIdx.x;
    if (e < E) {
        atomicAdd(&g_cnt_out[ei[e]], 1);      // src -> out-degree (normalization)
        atomicAdd(&g_cnt_in[ei[E + e]], 1);   // dst -> in-degree (CSR)
    }
}

// Fused scan: block-local shuffle scan + one atomic segment allocation per block.
// CSR segments need to be disjoint, not ordered by node id.
__global__ void alloc_scan_kernel(int n) {
    __shared__ int wsum[32];
    __shared__ int sbase;
    int t = threadIdx.x, lane = t & 31, w = t >> 5;
    int gid = blockIdx.x * 1024 + t;
    int v = (gid < n) ? g_cnt_in[gid] : 0;
    int x = v;
    #pragma unroll
    for (int d = 1; d < 32; d <<= 1) {
        int y = __shfl_up_sync(0xFFFFFFFFu, x, d);
        if (lane >= d) x += y;
    }
    if (lane == 31) wsum[w] = x;
    __syncthreads();
    if (w == 0) {
        int s = wsum[lane];
        int xs = s;
        #pragma unroll
        for (int d = 1; d < 32; d <<= 1) {
            int y = __shfl_up_sync(0xFFFFFFFFu, xs, d);
            if (lane >= d) xs += y;
        }
        wsum[lane] = xs - s;  // exclusive warp offsets
    }
    __syncthreads();
    int excl = x - v + wsum[w];
    if (t == 1023) sbase = atomicAdd(&g_total, excl + v);
    __syncthreads();
    if (gid < n) {
        int base = sbase + excl;
        g_rowstart[gid] = base;
        g_cursor[gid] = base;
        int d = g_cnt_out[gid];
        g_dinv[gid] = 1.0f / (float)(d > 1 ? d : 1);
    }
}

__global__ void scatter_kernel(const int* __restrict__ ei, int E) {
    int e = blockIdx.x * blockDim.x + threadIdx.x;
    if (e < E) {
        int d = ei[E + e];
        int pos = atomicAdd(&g_cursor[d], 1);
        g_csr[pos] = ei[e];  // source ids grouped by dst
    }
}

// ---------------- tf32 mma.sync GEMM (persistent, 256 thr, 2 CTAs/SM) ----------------
// out_fp16[M,N_] = A[M,128] @ W[128,N_]   (deg_inv applied later in agg)
// BM=64. smem A: As[row][pos], stride SA=136 words, pos(k) = (k>>3)*8 + (k&3)*2 + ((k>>2)&1)
// smem B: Bs[((k>>3)*N_ + n)*8 + (k&3)*2 + ((k>>2)&1)]
#define SA 136

template <int N_, bool FIRST>
__global__ __launch_bounds__(256, 2)
void gemm_mma_kernel(const float* __restrict__ Ain, const float* __restrict__ W,
                     int M, int n_tiles) {
    extern __shared__ uint32_t smem[];
    uint32_t* As = smem;                  // 64 * SA
    uint32_t* Bs = smem + 64 * SA;        // 128 * N_

    __half* __restrict__ out = FIRST ? g_h1 : g_h2;

    constexpr int HALF = N_ / 2;
    constexpr int NT = HALF / 8;          // 8 for N=128, 4 for N=64
    const int tid = threadIdx.x;
    const int wid = tid >> 5;             // 0..7
    const int lane = tid & 31;
    const int qr = lane >> 2;
    const int qc = lane & 3;
    const int rg = wid & 3;               // row group (16 rows)
    const int cg = wid >> 2;              // col half

    // stage B once (tf32, permuted)
    for (int idx = tid; idx < 128 * N_; idx += 256) {
        int k = idx / N_;
        int n = idx - k * N_;
        Bs[(((k >> 3) * N_ + n) << 3) + ((k & 3) << 1) + ((k >> 2) & 1)] = cvt_tf32(W[idx]);
    }

    const int j2 = lane >> 1;             // k-block (8 wide) this lane-pair covers
    const int odd = lane & 1;

    // per-iteration tile load: 4 channels per lane (row = 128 ch)
    auto load_row = [&](int gr) -> float4 {
        if (gr >= M) return make_float4(0.f, 0.f, 0.f, 0.f);
        if constexpr (FIRST) {
            return *(const float4*)(Ain + (size_t)gr * 128 + lane * 4);
        } else {
            uint2 u = *(const uint2*)(g_hr + (size_t)gr * 128 + lane * 4);
            float2 a = __half22float2(*reinterpret_cast<__half2*>(&u.x));
            float2 b = __half22float2(*reinterpret_cast<__half2*>(&u.y));
            return make_float4(a.x, a.y, b.x, b.y);
        }
    };

    float4 regs[8];
    int t = blockIdx.x;
    if (t < n_tiles) {
        #pragma unroll
        for (int it = 0; it < 8; it++)
            regs[it] = load_row(t * 64 + wid + it * 8);
    }
    __syncthreads();   // B staged

    for (; t < n_tiles; ) {
        // ---- STS: lane-pair exchange -> conflict-free STS.128 ----
        #pragma unroll
        for (int it = 0; it < 8; it++) {
            int r = wid + it * 8;
            float4 v = regs[it];
            float ox = __shfl_xor_sync(0xFFFFFFFFu, v.x, 1);
            float oy = __shfl_xor_sync(0xFFFFFFFFu, v.y, 1);
            float oz = __shfl_xor_sync(0xFFFFFFFFu, v.z, 1);
            float ow = __shfl_xor_sync(0xFFFFFFFFu, v.w, 1);
            uint4 st;
            if (!odd) {
                st.x = cvt_tf32(v.x); st.y = cvt_tf32(ox);
                st.z = cvt_tf32(v.y); st.w = cvt_tf32(oy);
            } else {
                st.x = cvt_tf32(oz); st.y = cvt_tf32(v.z);
                st.z = cvt_tf32(ow); st.w = cvt_tf32(v.w);
            }
            *(uint4*)(As + r * SA + j2 * 8 + odd * 4) = st;
        }
        __syncthreads();

        // ---- prefetch next tile (overlaps compute) ----
        int tn = t + gridDim.x;
        if (tn < n_tiles) {
            #pragma unroll
            for (int it = 0; it < 8; it++)
                regs[it] = load_row(tn * 64 + wid + it * 8);
        }

        // ---- compute ----
        float acc[NT][4];
        #pragma unroll
        for (int nt = 0; nt < NT; nt++)
            #pragma unroll
            for (int j = 0; j < 4; j++) acc[nt][j] = 0.f;

        #pragma unroll
        for (int s = 0; s < 16; s++) {
            uint32_t a[4];
            const uint32_t* pa = As + (rg * 16 + qr) * SA + s * 8 + qc * 2;
            uint2 lo = *(const uint2*)pa;
            uint2 hi = *(const uint2*)(pa + 8 * SA);
            a[0] = lo.x; a[1] = hi.x; a[2] = lo.y; a[3] = hi.y;
            const uint32_t* pb = Bs + ((s * N_ + cg * HALF + qr) << 3) + qc * 2;
            #pragma unroll
            for (int nt = 0; nt < NT; nt++) {
                uint2 bb = *(const uint2*)(pb + (nt << 6));
                uint32_t b[2] = {bb.x, bb.y};
                mma_tf32(acc[nt], a, b);
            }
        }

        // ---- epilogue: fp16 store ----
        {
            int r0 = t * 64 + rg * 16 + qr;
            int r1 = r0 + 8;
            #pragma unroll
            for (int nt = 0; nt < NT; nt++) {
                int c = cg * HALF + nt * 8 + qc * 2;
                if (r0 < M)
                    *(__half2*)(out + (size_t)r0 * N_ + c) = __floats2half2_rn(acc[nt][0], acc[nt][1]);
                if (r1 < M)
                    *(__half2*)(out + (size_t)r1 * N_ + c) = __floats2half2_rn(acc[nt][2], acc[nt][3]);
            }
        }
        __syncthreads();
        t = tn;
    }
}

// ---------------- aggregation: warp per dst node, 8-deep gather pipeline ----------------
// FIRST: out = relu(sum + b1) -> g_hr (fp16).  else: out = sum + b2 -> d_out (fp32)
template <int C, bool FIRST>
__global__ void agg_kernel(const float* __restrict__ bias, float* __restrict__ outp, int n) {
    int gw = (blockIdx.x * blockDim.x + threadIdx.x) >> 5;
    int lane = threadIdx.x & 31;
    if (gw >= n) return;

    const __half* __restrict__ h = FIRST ? g_h1 : g_h2;

    int beg = g_rowstart[gw];
    int m = g_cnt_in[gw];

    if constexpr (C == 128) {
        size_t off = (size_t)lane * 4;
        float4 acc = make_float4(0.f, 0.f, 0.f, 0.f);
        int e = 0;
        for (; e + 8 <= m; e += 8) {
            int idx[8];
            uint2 u[8];
            float d[8];
            #pragma unroll
            for (int j = 0; j < 8; j++) idx[j] = g_csr[beg + e + j];
            #pragma unroll
            for (int j = 0; j < 8; j++) u[j] = *(const uint2*)(h + (size_t)idx[j] * C + off);
            #pragma unroll
            for (int j = 0; j < 8; j++) d[j] = __ldg(&g_dinv[idx[j]]);
            #pragma unroll
            for (int j = 0; j < 8; j++) {
                float2 a0 = __half22float2(*reinterpret_cast<__half2*>(&u[j].x));
                float2 a1 = __half22float2(*reinterpret_cast<__half2*>(&u[j].y));
                acc.x = fmaf(a0.x, d[j], acc.x);
                acc.y = fmaf(a0.y, d[j], acc.y);
                acc.z = fmaf(a1.x, d[j], acc.z);
                acc.w = fmaf(a1.y, d[j], acc.w);
            }
        }
        for (; e + 2 <= m; e += 2) {
            int s0 = g_csr[beg + e];
            int s1 = g_csr[beg + e + 1];
            uint2 u0 = *(const uint2*)(h + (size_t)s0 * C + off);
            uint2 u1 = *(const uint2*)(h + (size_t)s1 * C + off);
            float d0 = __ldg(&g_dinv[s0]);
            float d1 = __ldg(&g_dinv[s1]);
            float2 a0 = __half22float2(*reinterpret_cast<__half2*>(&u0.x));
            float2 a1 = __half22float2(*reinterpret_cast<__half2*>(&u0.y));
            float2 b0 = __half22float2(*reinterpret_cast<__half2*>(&u1.x));
            float2 b1 = __half22float2(*reinterpret_cast<__half2*>(&u1.y));
            acc.x = fmaf(a0.x, d0, fmaf(b0.x, d1, acc.x));
            acc.y = fmaf(a0.y, d0, fmaf(b0.y, d1, acc.y));
            acc.z = fmaf(a1.x, d0, fmaf(b1.x, d1, acc.z));
            acc.w = fmaf(a1.y, d0, fmaf(b1.y, d1, acc.w));
        }
        if (e < m) {
            int s = g_csr[beg + e];
            float d = __ldg(&g_dinv[s]);
            uint2 u = *(const uint2*)(h + (size_t)s * C + off);
            float2 a0 = __half22float2(*reinterpret_cast<__half2*>(&u.x));
            float2 a1 = __half22float2(*reinterpret_cast<__half2*>(&u.y));
            acc.x = fmaf(a0.x, d, acc.x); acc.y = fmaf(a0.y, d, acc.y);
            acc.z = fmaf(a1.x, d, acc.z); acc.w = fmaf(a1.y, d, acc.w);
        }
        float4 bb = *(const float4*)(bias + lane * 4);
        acc.x += bb.x; acc.y += bb.y; acc.z += bb.z; acc.w += bb.w;
        if constexpr (FIRST) {
            acc.x = fmaxf(acc.x, 0.f); acc.y = fmaxf(acc.y, 0.f);
            acc.z = fmaxf(acc.z, 0.f); acc.w = fmaxf(acc.w, 0.f);
            uint2 st;
            *reinterpret_cast<__half2*>(&st.x) = __floats2half2_rn(acc.x, acc.y);
            *reinterpret_cast<__half2*>(&st.y) = __floats2half2_rn(acc.z, acc.w);
            *(uint2*)(g_hr + (size_t)gw * C + off) = st;
        } else {
            *(float4*)(outp + (size_t)gw * C + off) = acc;
        }
    } else {
        size_t off = (size_t)lane * 2;
        float2 acc = make_float2(0.f, 0.f);
        int e = 0;
        for (; e + 8 <= m; e += 8) {
            int idx[8];
            uint32_t u[8];
            float d[8];
            #pragma unroll
            for (int j = 0; j < 8; j++) idx[j] = g_csr[beg + e + j];
            #pragma unroll
            for (int j = 0; j < 8; j++) u[j] = *(const uint32_t*)(h + (size_t)idx[j] * C + off);
            #pragma unroll
            for (int j = 0; j < 8; j++) d[j] = __ldg(&g_dinv[idx[j]]);
            #pragma unroll
            for (int j = 0; j < 8; j++) {
                float2 a = __half22float2(*reinterpret_cast<__half2*>(&u[j]));
                acc.x = fmaf(a.x, d[j], acc.x);
                acc.y = fmaf(a.y, d[j], acc.y);
            }
        }
        for (; e < m; e++) {
            int s = g_csr[beg + e];
            float d = __ldg(&g_dinv[s]);
            uint32_t u = *(const uint32_t*)(h + (size_t)s * C + off);
            float2 a = __half22float2(*reinterpret_cast<__half2*>(&u));
            acc.x = fmaf(a.x, d, acc.x); acc.y = fmaf(a.y, d, acc.y);
        }
        float2 bb = *(const float2*)(bias + lane * 2);
        acc.x += bb.x; acc.y += bb.y;
        *(float2*)(outp + (size_t)gw * C + off) = acc;
    }
}

// ---------------- launch ----------------
extern "C" void kernel_launch(void* const* d_in, const int* in_sizes, int n_in,
                              void* d_out, int out_size) {
    const float* x  = (const float*)d_in[0];
    const int*   ei = (const int*)d_in[1];
    const float* W1 = (const float*)d_in[2];
    const float* b1 = (const float*)d_in[3];
    const float* W2 = (const float*)d_in[4];
    const float* b2 = (const float*)d_in[5];
    float* out = (float*)d_out;

    int N = in_sizes[0] / INC;   // 100000
    int E = in_sizes[1] / 2;     // 1600000

    int nb1k = (N + 1023) / 1024;
    int n_tiles = (N + 63) / 64;

    const int SMEM1 = (64 * SA + 128 * HIDC) * 4;   // 100352 (~98KB)
    const int SMEM2 = (64 * SA + 128 * OUTC) * 4;   // 67584  (~66KB)

    static int sm_count = 0;
    static cudaStream_t s2 = nullptr;
    static cudaEvent_t evFork = nullptr, evCsr = nullptr;
    static void *p_cnt_in = nullptr, *p_cnt_out = nullptr, *p_total = nullptr;
    static bool init_ok = false;
    if (!init_ok) {
        int dev = 0, c = 0;
        cudaGetDevice(&dev);
        if (cudaDeviceGetAttribute(&c, cudaDevAttrMultiProcessorCount, dev) != cudaSuccess || c <= 0)
            c = 148;
        sm_count = c;
        cudaFuncSetAttribute(gemm_mma_kernel<HIDC, true>,
                             cudaFuncAttributeMaxDynamicSharedMemorySize, SMEM1);
        cudaFuncSetAttribute(gemm_mma_kernel<OUTC, false>,
                             cudaFuncAttributeMaxDynamicSharedMemorySize, SMEM2);
        cudaStreamCreateWithFlags(&s2, cudaStreamNonBlocking);
        cudaEventCreateWithFlags(&evFork, cudaEventDisableTiming);
        cudaEventCreateWithFlags(&evCsr,  cudaEventDisableTiming);
        cudaGetSymbolAddress(&p_cnt_in,  g_cnt_in);
        cudaGetSymbolAddress(&p_cnt_out, g_cnt_out);
        cudaGetSymbolAddress(&p_total,   g_total);
        init_ok = true;
    }

    int gemm_grid = 2 * sm_count;   // 2 CTAs/SM

    // ---- fork: CSR chain on s2 (atomics/latency-bound), GEMM1 on main (DRAM/tensor) ----
    cudaEventRecord(evFork, 0);
    cudaStreamWaitEvent(s2, evFork, 0);

    cudaMemsetAsync(p_cnt_in,  0, (size_t)N * sizeof(int), s2);
    cudaMemsetAsync(p_cnt_out, 0, (size_t)N * sizeof(int), s2);
    cudaMemsetAsync(p_total,   0, sizeof(int), s2);
    hist_kernel<<<(E + 255) / 256, 256, 0, s2>>>(ei, E);
    alloc_scan_kernel<<<nb1k, 1024, 0, s2>>>(N);
    scatter_kernel<<<(E + 255) / 256, 256, 0, s2>>>(ei, E);
    cudaEventRecord(evCsr, s2);

    gemm_mma_kernel<HIDC, true><<<gemm_grid, 256, SMEM1, 0>>>(x, W1, N, n_tiles);

    // ---- join, then serial memory-bound tail ----
    cudaStreamWaitEvent(0, evCsr, 0);
    agg_kernel<HIDC, true><<<((size_t)N * 32 + 255) / 256, 256, 0, 0>>>(b1, nullptr, N);
    gemm_mma_kernel<OUTC, false><<<gemm_grid, 256, SMEM2, 0>>>(nullptr, W2, N, n_tiles);
    agg_kernel<OUTC, false><<<((size_t)N * 32 + 255) / 256, 256, 0, 0>>>(b2, out, N);
}

// round 8
// speedup vs baseline: 1.3266x; 1.0840x over previous
#include <cuda_runtime.h>
#include <cuda_fp16.h>
#include <cstdint>

// Problem shape (fixed by the dataset)
#define NMAX 100000
#define EMAX 1600000
#define INC 128
#define HIDC 128
#define OUTC 64

// ---------------- scratch (no allocation allowed) ----------------
__device__ __half g_h1[(size_t)NMAX * HIDC];  // x@W1 (unscaled, fp16)
__device__ __half g_hr[(size_t)NMAX * HIDC];  // relu(agg1 + b1), fp16
__device__ __half g_h2[(size_t)NMAX * OUTC];  // hr@W2 (unscaled, fp16)
__device__ float  g_dinv[NMAX];
__device__ int    g_cnt_in[NMAX];
__device__ int    g_cnt_out[NMAX];
__device__ int    g_rowstart[NMAX];
__device__ int    g_cursor[NMAX];
__device__ int    g_total;
__device__ int    g_csr[EMAX];

// ---------------- helpers ----------------
__device__ __forceinline__ uint32_t pack_half2(float a, float b) {
    __half2 h = __floats2half2_rn(a, b);
    return *reinterpret_cast<uint32_t*>(&h);
}

__device__ __forceinline__ void mma_fp16(float* c, uint32_t a0, uint32_t a1,
                                         uint32_t a2, uint32_t a3,
                                         uint32_t b0, uint32_t b1) {
    asm volatile(
        "mma.sync.aligned.m16n8k16.row.col.f32.f16.f16.f32 "
        "{%0,%1,%2,%3}, {%4,%5,%6,%7}, {%8,%9}, {%0,%1,%2,%3};"
        : "+f"(c[0]), "+f"(c[1]), "+f"(c[2]), "+f"(c[3])
        : "r"(a0), "r"(a1), "r"(a2), "r"(a3), "r"(b0), "r"(b1));
}

// ---------------- CSR build ----------------
__global__ void hist_kernel(const int* __restrict__ ei, int E) {
    int e = blockIdx.x * blockDim.x + threadIdx.x;
    if (e < E) {
        atomicAdd(&g_cnt_out[ei[e]], 1);      // src -> out-degree (normalization)
        atomicAdd(&g_cnt_in[ei[E + e]], 1);   // dst -> in-degree (CSR)
    }
}

// Fused scan: block-local shuffle scan + one atomic segment allocation per block.
__global__ void alloc_scan_kernel(int n) {
    __shared__ int wsum[32];
    __shared__ int sbase;
    int t = threadIdx.x, lane = t & 31, w = t >> 5;
    int gid = blockIdx.x * 1024 + t;
    int v = (gid < n) ? g_cnt_in[gid] : 0;
    int x = v;
    #pragma unroll
    for (int d = 1; d < 32; d <<= 1) {
        int y = __shfl_up_sync(0xFFFFFFFFu, x, d);
        if (lane >= d) x += y;
    }
    if (lane == 31) wsum[w] = x;
    __syncthreads();
    if (w == 0) {
        int s = wsum[lane];
        int xs = s;
        #pragma unroll
        for (int d = 1; d < 32; d <<= 1) {
            int y = __shfl_up_sync(0xFFFFFFFFu, xs, d);
            if (lane >= d) xs += y;
        }
        wsum[lane] = xs - s;
    }
    __syncthreads();
    int excl = x - v + wsum[w];
    if (t == 1023) sbase = atomicAdd(&g_total, excl + v);
    __syncthreads();
    if (gid < n) {
        int base = sbase + excl;
        g_rowstart[gid] = base;
        g_cursor[gid] = base;
        int d = g_cnt_out[gid];
        g_dinv[gid] = 1.0f / (float)(d > 1 ? d : 1);
    }
}

__global__ void scatter_kernel(const int* __restrict__ ei, int E) {
    int e = blockIdx.x * blockDim.x + threadIdx.x;
    if (e < E) {
        int d = ei[E + e];
        int pos = atomicAdd(&g_cursor[d], 1);
        g_csr[pos] = ei[e];
    }
}

// ---------------- fp16 mma.sync m16n8k16 GEMM (persistent, 256 thr, 2 CTAs/SM) ----------
// out_fp16[M,N_] = A[M,128] @ W[128,N_]
// Data as fp16x2 "units" (unit u = channels 2u,2u+1).
// A smem: row stride 68 words; unit u at word row*68 + (u>>3)*8 + p(u&7),
//   p(v) = v<4 ? 2v : 2(v-4)+1  -> LDS.64 at qc*2 grabs k-units {qc, qc+4} = {a_lo, a_hi}.
// B smem: unit (n,u) at word ((u>>3)*N_ + n)*8 + p(u&7)  (B = W^T, k-major per col).
#define SAW 68   // A row stride in words

template <int N_, bool FIRST>
__global__ __launch_bounds__(256, 2)
void gemm_mma_kernel(const float* __restrict__ Ain, const float* __restrict__ W,
                     int M, int n_tiles) {
    extern __shared__ uint32_t smem[];
    uint32_t* As = smem;                  // 64 * SAW words
    uint32_t* Bs = smem + 64 * SAW;       // 64 * N_ words

    __half* __restrict__ out = FIRST ? g_h1 : g_h2;

    constexpr int HALF = N_ / 2;
    constexpr int NT = HALF / 8;          // 8 for N=128, 4 for N=64
    const int tid = threadIdx.x;
    const int wid = tid >> 5;             // 0..7
    const int lane = tid & 31;
    const int qr = lane >> 2;
    const int qc = lane & 3;
    const int rg = wid & 3;               // row group (16 rows)
    const int cg = wid >> 2;              // col half

    // ---- stage B once: unit (u, n) -> half2(W[2u][n], W[2u+1][n]) ----
    for (int uidx = tid; uidx < 64 * N_; uidx += 256) {
        int u = uidx / N_;
        int n = uidx - u * N_;
        uint32_t val = pack_half2(W[(size_t)(2 * u) * N_ + n], W[(size_t)(2 * u + 1) * N_ + n]);
        int v = u & 7;
        int p = (v < 4) ? (2 * v) : (2 * (v - 4) + 1);
        Bs[(((u >> 3) * N_ + n) << 3) + p] = val;
    }

    const int sg = lane >> 2;             // store row-group helper = qr
    const int sj = lane & 3;

    // per-row load: lane covers channels 4*lane..4*lane+3 = units 2*lane, 2*lane+1
    auto load_row = [&](int gr, uint32_t& r0, uint32_t& r1) {
        if (gr >= M) { r0 = 0u; r1 = 0u; return; }
        if constexpr (FIRST) {
            float4 v = *(const float4*)(Ain + (size_t)gr * 128 + lane * 4);
            r0 = pack_half2(v.x, v.y);
            r1 = pack_half2(v.z, v.w);
        } else {
            uint2 u = *(const uint2*)(g_hr + (size_t)gr * 128 + lane * 4);
            r0 = u.x; r1 = u.y;
        }
    };

    uint32_t pr0[8], pr1[8];
    int t = blockIdx.x;
    if (t < n_tiles) {
        #pragma unroll
        for (int it = 0; it < 8; it++)
            load_row(t * 64 + wid + it * 8, pr0[it], pr1[it]);
    }
    __syncthreads();   // B staged

    for (; t < n_tiles; ) {
        // ---- STS: lane-pair (xor 2) exchange -> 16B chunks, conflict-floor STS.128 ----
        // lane = 4g + j holds units 8g+2j, 8g+2j+1.
        // chunk low  (words g*8+0..3) = {j0.r0, j2.r0, j0.r1, j2.r1}
        // chunk high (words g*8+4..7) = {j1.r0, j3.r0, j1.r1, j3.r1}
        #pragma unroll
        for (int it = 0; it < 8; it++) {
            int r = wid + it * 8;
            uint32_t o0 = __shfl_xor_sync(0xFFFFFFFFu, pr0[it], 2);
            uint32_t o1 = __shfl_xor_sync(0xFFFFFFFFu, pr1[it], 2);
            if ((sj & 2) == 0) {
                uint4 st;
                st.x = pr0[it]; st.y = o0; st.z = pr1[it]; st.w = o1;
                *(uint4*)(As + r * SAW + sg * 8 + (sj & 1) * 4) = st;
            }
        }
        __syncthreads();

        // ---- prefetch next tile (overlaps compute) ----
        int tn = t + gridDim.x;
        if (tn < n_tiles) {
            #pragma unroll
            for (int it = 0; it < 8; it++)
                load_row(tn * 64 + wid + it * 8, pr0[it], pr1[it]);
        }

        // ---- compute: 8 k16-steps ----
        float acc[NT][4];
        #pragma unroll
        for (int nt = 0; nt < NT; nt++)
            #pragma unroll
            for (int j = 0; j < 4; j++) acc[nt][j] = 0.f;

        #pragma unroll
        for (int s = 0; s < 8; s++) {
            const uint32_t* pa = As + (rg * 16 + qr) * SAW + s * 8 + qc * 2;
            uint2 A0 = *(const uint2*)pa;              // {a0, a2}: row qr, k lo/hi
            uint2 A1 = *(const uint2*)(pa + 8 * SAW);  // {a1, a3}: row qr+8
            const uint32_t* pb = Bs + (((s * N_) + cg * HALF + qr) << 3) + qc * 2;
            #pragma unroll
            for (int nt = 0; nt < NT; nt++) {
                uint2 B0 = *(const uint2*)(pb + (nt << 6));  // {b0, b1}
                mma_fp16(acc[nt], A0.x, A1.x, A0.y, A1.y, B0.x, B0.y);
            }
        }

        // ---- epilogue: fp16 store ----
        {
            int r0 = t * 64 + rg * 16 + qr;
            int r1 = r0 + 8;
            #pragma unroll
            for (int nt = 0; nt < NT; nt++) {
                int c = cg * HALF + nt * 8 + qc * 2;
                if (r0 < M)
                    *(__half2*)(out + (size_t)r0 * N_ + c) = __floats2half2_rn(acc[nt][0], acc[nt][1]);
                if (r1 < M)
                    *(__half2*)(out + (size_t)r1 * N_ + c) = __floats2half2_rn(acc[nt][2], acc[nt][3]);
            }
        }
        __syncthreads();
        t = tn;
    }
}

// ---------------- aggregation: warp per dst node, 8-deep gather pipeline ----------------
template <int C, bool FIRST>
__global__ void agg_kernel(const float* __restrict__ bias, float* __restrict__ outp, int n) {
    int gw = (blockIdx.x * blockDim.x + threadIdx.x) >> 5;
    int lane = threadIdx.x & 31;
    if (gw >= n) return;

    const __half* __restrict__ h = FIRST ? g_h1 : g_h2;

    int beg = g_rowstart[gw];
    int m = g_cnt_in[gw];

    if constexpr (C == 128) {
        size_t off = (size_t)lane * 4;
        float4 acc = make_float4(0.f, 0.f, 0.f, 0.f);
        int e = 0;
        for (; e + 8 <= m; e += 8) {
            int idx[8];
            uint2 u[8];
            float d[8];
            #pragma unroll
            for (int j = 0; j < 8; j++) idx[j] = g_csr[beg + e + j];
            #pragma unroll
            for (int j = 0; j < 8; j++) u[j] = *(const uint2*)(h + (size_t)idx[j] * C + off);
            #pragma unroll
            for (int j = 0; j < 8; j++) d[j] = __ldg(&g_dinv[idx[j]]);
            #pragma unroll
            for (int j = 0; j < 8; j++) {
                float2 a0 = __half22float2(*reinterpret_cast<__half2*>(&u[j].x));
                float2 a1 = __half22float2(*reinterpret_cast<__half2*>(&u[j].y));
                acc.x = fmaf(a0.x, d[j], acc.x);
                acc.y = fmaf(a0.y, d[j], acc.y);
                acc.z = fmaf(a1.x, d[j], acc.z);
                acc.w = fmaf(a1.y, d[j], acc.w);
            }
        }
        for (; e + 2 <= m; e += 2) {
            int s0 = g_csr[beg + e];
            int s1 = g_csr[beg + e + 1];
            uint2 u0 = *(const uint2*)(h + (size_t)s0 * C + off);
            uint2 u1 = *(const uint2*)(h + (size_t)s1 * C + off);
            float d0 = __ldg(&g_dinv[s0]);
            float d1 = __ldg(&g_dinv[s1]);
            float2 a0 = __half22float2(*reinterpret_cast<__half2*>(&u0.x));
            float2 a1 = __half22float2(*reinterpret_cast<__half2*>(&u0.y));
            float2 b0 = __half22float2(*reinterpret_cast<__half2*>(&u1.x));
            float2 b1 = __half22float2(*reinterpret_cast<__half2*>(&u1.y));
            acc.x = fmaf(a0.x, d0, fmaf(b0.x, d1, acc.x));
            acc.y = fmaf(a0.y, d0, fmaf(b0.y, d1, acc.y));
            acc.z = fmaf(a1.x, d0, fmaf(b1.x, d1, acc.z));
            acc.w = fmaf(a1.y, d0, fmaf(b1.y, d1, acc.w));
        }
        if (e < m) {
            int s = g_csr[beg + e];
            float d = __ldg(&g_dinv[s]);
            uint2 u = *(const uint2*)(h + (size_t)s * C + off);
            float2 a0 = __half22float2(*reinterpret_cast<__half2*>(&u.x));
            float2 a1 = __half22float2(*reinterpret_cast<__half2*>(&u.y));
            acc.x = fmaf(a0.x, d, acc.x); acc.y = fmaf(a0.y, d, acc.y);
            acc.z = fmaf(a1.x, d, acc.z); acc.w = fmaf(a1.y, d, acc.w);
        }
        float4 bb = *(const float4*)(bias + lane * 4);
        acc.x += bb.x; acc.y += bb.y; acc.z += bb.z; acc.w += bb.w;
        if constexpr (FIRST) {
            acc.x = fmaxf(acc.x, 0.f); acc.y = fmaxf(acc.y, 0.f);
            acc.z = fmaxf(acc.z, 0.f); acc.w = fmaxf(acc.w, 0.f);
            uint2 st;
            *reinterpret_cast<__half2*>(&st.x) = __floats2half2_rn(acc.x, acc.y);
            *reinterpret_cast<__half2*>(&st.y) = __floats2half2_rn(acc.z, acc.w);
            *(uint2*)(g_hr + (size_t)gw * C + off) = st;
        } else {
            *(float4*)(outp + (size_t)gw * C + off) = acc;
        }
    } else {
        size_t off = (size_t)lane * 2;
        float2 acc = make_float2(0.f, 0.f);
        int e = 0;
        for (; e + 8 <= m; e += 8) {
            int idx[8];
            uint32_t u[8];
            float d[8];
            #pragma unroll
            for (int j = 0; j < 8; j++) idx[j] = g_csr[beg + e + j];
            #pragma unroll
            for (int j = 0; j < 8; j++) u[j] = *(const uint32_t*)(h + (size_t)idx[j] * C + off);
            #pragma unroll
            for (int j = 0; j < 8; j++) d[j] = __ldg(&g_dinv[idx[j]]);
            #pragma unroll
            for (int j = 0; j < 8; j++) {
                float2 a = __half22float2(*reinterpret_cast<__half2*>(&u[j]));
                acc.x = fmaf(a.x, d[j], acc.x);
                acc.y = fmaf(a.y, d[j], acc.y);
            }
        }
        for (; e < m; e++) {
            int s = g_csr[beg + e];
            float d = __ldg(&g_dinv[s]);
            uint32_t u = *(const uint32_t*)(h + (size_t)s * C + off);
            float2 a = __half22float2(*reinterpret_cast<__half2*>(&u));
            acc.x = fmaf(a.x, d, acc.x); acc.y = fmaf(a.y, d, acc.y);
        }
        float2 bb = *(const float2*)(bias + lane * 2);
        acc.x += bb.x; acc.y += bb.y;
        *(float2*)(outp + (size_t)gw * C + off) = acc;
    }
}

// ---------------- launch ----------------
extern "C" void kernel_launch(void* const* d_in, const int* in_sizes, int n_in,
                              void* d_out, int out_size) {
    const float* x  = (const float*)d_in[0];
    const int*   ei = (const int*)d_in[1];
    const float* W1 = (const float*)d_in[2];
    const float* b1 = (const float*)d_in[3];
    const float* W2 = (const float*)d_in[4];
    const float* b2 = (const float*)d_in[5];
    float* out = (float*)d_out;

    int N = in_sizes[0] / INC;   // 100000
    int E = in_sizes[1] / 2;     // 1600000

    int nb1k = (N + 1023) / 1024;
    int n_tiles = (N + 63) / 64;

    const int SMEM1 = (64 * SAW + 64 * HIDC) * 4;   // 50176 (~49KB)
    const int SMEM2 = (64 * SAW + 64 * OUTC) * 4;   // 33792 (~33KB)

    static int sm_count = 0;
    static cudaStream_t s2 = nullptr;
    static cudaEvent_t evFork = nullptr, evCsr = nullptr;
    static void *p_cnt_in = nullptr, *p_cnt_out = nullptr, *p_total = nullptr;
    static bool init_ok = false;
    if (!init_ok) {
        int dev = 0, c = 0;
        cudaGetDevice(&dev);
        if (cudaDeviceGetAttribute(&c, cudaDevAttrMultiProcessorCount, dev) != cudaSuccess || c <= 0)
            c = 148;
        sm_count = c;
        cudaFuncSetAttribute(gemm_mma_kernel<HIDC, true>,
                             cudaFuncAttributeMaxDynamicSharedMemorySize, SMEM1);
        cudaFuncSetAttribute(gemm_mma_kernel<OUTC, false>,
                             cudaFuncAttributeMaxDynamicSharedMemorySize, SMEM2);
        cudaStreamCreateWithFlags(&s2, cudaStreamNonBlocking);
        cudaEventCreateWithFlags(&evFork, cudaEventDisableTiming);
        cudaEventCreateWithFlags(&evCsr,  cudaEventDisableTiming);
        cudaGetSymbolAddress(&p_cnt_in,  g_cnt_in);
        cudaGetSymbolAddress(&p_cnt_out, g_cnt_out);
        cudaGetSymbolAddress(&p_total,   g_total);
        init_ok = true;
    }

    int gemm_grid = 2 * sm_count;   // 2 CTAs/SM

    // ---- fork: CSR chain on s2 (atomics/latency-bound), GEMM1 on main (DRAM/tensor) ----
    cudaEventRecord(evFork, 0);
    cudaStreamWaitEvent(s2, evFork, 0);

    cudaMemsetAsync(p_cnt_in,  0, (size_t)N * sizeof(int), s2);
    cudaMemsetAsync(p_cnt_out, 0, (size_t)N * sizeof(int), s2);
    cudaMemsetAsync(p_total,   0, sizeof(int), s2);
    hist_kernel<<<(E + 255) / 256, 256, 0, s2>>>(ei, E);
    alloc_scan_kernel<<<nb1k, 1024, 0, s2>>>(N);
    scatter_kernel<<<(E + 255) / 256, 256, 0, s2>>>(ei, E);
    cudaEventRecord(evCsr, s2);

    gemm_mma_kernel<HIDC, true><<<gemm_grid, 256, SMEM1, 0>>>(x, W1, N, n_tiles);

    // ---- join, then serial memory-bound tail ----
    cudaStreamWaitEvent(0, evCsr, 0);
    agg_kernel<HIDC, true><<<((size_t)N * 32 + 255) / 256, 256, 0, 0>>>(b1, nullptr, N);
    gemm_mma_kernel<OUTC, false><<<gemm_grid, 256, SMEM2, 0>>>(nullptr, W2, N, n_tiles);
    agg_kernel<OUTC, false><<<((size_t)N * 32 + 255) / 256, 256, 0, 0>>>(b2, out, N);
}